// round 15
// baseline (speedup 1.0000x reference)
#include <cuda_runtime.h>
#include <cuda_bf16.h>
#include <cstdint>

// SpikeEncoder: rates = sigmoid(x @ W^T + b); spikes = (u < rates)
// x: [256,512] f32, W: [2048,512] f32, b: [2048] f32, u: [256,100,2048] f32
// out: spikes [256*100*2048] f32, then rates [256*2048] f32

#define BATCH 256
#define INPUT_DIM 512
#define NUM_NEURONS 2048
#define TIME_STEPS 100

#define TBM 32                     // GEMM tile rows
#define TBN 64
#define TBK 32
#define NTILES (INPUT_DIM / TBK)   // 16

#define ROWF 36                    // padded floats per smem row (bank-bijective)
#define TILEF_A (TBM * ROWF)       // 1152
#define TILEF_B (TBN * ROWF)       // 2304
#define OFF_ALO  TILEF_A
#define OFF_BHI  (2 * TILEF_A)
#define OFF_BLO  (2 * TILEF_A + TILEF_B)
#define BUFF (2 * TILEF_A + 2 * TILEF_B)   // 6912 floats
#define SMEM_BYTES (2 * BUFF * 4)          // 55296 bytes

// u prefetch: 96MB = first ~46% of u, in spike-dispatch order (low b first)
#define PF_BLOCKS 768              // 768 blocks * 256 thr * 4 lines * 128B = 96MB

// fp32 -> tf32 split via mantissa mask: hi = one LOP3 (exact, hi+lo == v);
// lo rounded to tf32 (cvt.rna) -> representation err ~2^-21|v|.
__device__ __forceinline__ void tf32_split(float v, float& h, float& l) {
    const float hf = __uint_as_float(__float_as_uint(v) & 0xFFFFE000u);
    uint32_t lb;
    asm("cvt.rna.tf32.f32 %0, %1;" : "=r"(lb) : "f"(v - hf));
    h = hf;
    l = __uint_as_float(lb);
}

__device__ __forceinline__ void cvt_store(float* __restrict__ hi,
                                          float* __restrict__ lo,
                                          int off, float4 v) {
    float4 h, l;
    tf32_split(v.x, h.x, l.x);
    tf32_split(v.y, h.y, l.y);
    tf32_split(v.z, h.z, l.z);
    tf32_split(v.w, h.w, l.w);
    *(float4*)&hi[off] = h;
    *(float4*)&lo[off] = l;
}

// D += A(tf32, m16k8 row) x B(tf32, k8n8 col)
__device__ __forceinline__ void mma_tf32(float c[4],
                                         uint32_t a0, uint32_t a1,
                                         uint32_t a2, uint32_t a3,
                                         uint32_t b0, uint32_t b1) {
    asm volatile(
        "mma.sync.aligned.m16n8k8.row.col.f32.tf32.tf32.f32 "
        "{%0,%1,%2,%3}, {%4,%5,%6,%7}, {%8,%9}, {%0,%1,%2,%3};"
        : "+f"(c[0]), "+f"(c[1]), "+f"(c[2]), "+f"(c[3])
        : "r"(a0), "r"(a1), "r"(a2), "r"(a3), "r"(b0), "r"(b1));
}

// ---------------------------------------------------------------------------
// Prefetch kernel (side stream, concurrent with the GEMM): pulls the first
// 96MB of u into L2 using otherwise-idle DRAM bandwidth. Pure hint — no
// data dependencies. Covers the u region the spike grid consumes first.
// ---------------------------------------------------------------------------
__global__ __launch_bounds__(256)
void prefetch_kernel(const char* __restrict__ u) {
    const long long base = ((long long)blockIdx.x * 1024 + threadIdx.x * 4) * 128;
#pragma unroll
    for (int l = 0; l < 4; l++)
        asm volatile("prefetch.global.L2 [%0];" :: "l"(u + base + l * 128));
}

// ---------------------------------------------------------------------------
// GEMM: rates = sigmoid(x @ W^T + b). EXACT math of the R11/R12/R13 kernel
// (bit-stable rel_err 3.901189e-4 across three rounds): 32x64 tile,
// split-at-store (mask hi + cvt.rna lo), double-buffered smem, tf32 MMA
// with 3-term compensation, hi*hi split even/odd-k8 (c0/c1) against RZ
// accumulation bias, cross terms in cx, RN combine at epilogue.
// Single pass, grid (32, 8) = 256 blocks (one wave), 256 threads, 8 warps.
// ---------------------------------------------------------------------------
__global__ __launch_bounds__(256)
void rates_kernel(const float* __restrict__ x,
                  const float* __restrict__ W,
                  const float* __restrict__ bias,
                  float* __restrict__ rates) {
    extern __shared__ float sm[];

    const int tid  = threadIdx.x;
    const int warp = tid >> 5;
    const int lane = tid & 31;
    const int g = lane >> 2;
    const int q = lane & 3;
    const int mb = warp & 1;       // m16 block (0..1)
    const int nh = warp >> 1;      // n16 group (0..3)

    const int nBase = blockIdx.x * TBN;
    const int mBase = blockIdx.y * TBM;

    // Cooperative-load coords. A: 256 float4/tile (1/thread); B: 512 (2/thread)
    const int rowA = tid >> 3;             // 0..31
    const int kcA  = (tid & 7) * 4;
    int rowB[2], kcB[2];
#pragma unroll
    for (int l = 0; l < 2; l++) {
        const int f = tid + l * 256;
        rowB[l] = f >> 3;                  // 0..63
        kcB[l]  = (f & 7) * 4;
    }

    const int ar0 = (mb * 16 + g) * ROWF;
    const int ar1 = ar0 + 8 * ROWF;

    // Prologue: tile 0 -> regs -> split -> smem buf 0
    float4 xa = *(const float4*)&x[(mBase + rowA) * INPUT_DIM + kcA];
    float4 wb[2];
#pragma unroll
    for (int l = 0; l < 2; l++)
        wb[l] = *(const float4*)&W[(nBase + rowB[l]) * INPUT_DIM + kcB[l]];
    {
        float* buf = sm;
        cvt_store(buf, buf + OFF_ALO, rowA * ROWF + kcA, xa);
#pragma unroll
        for (int l = 0; l < 2; l++)
            cvt_store(buf + OFF_BHI, buf + OFF_BLO, rowB[l] * ROWF + kcB[l], wb[l]);
    }
    __syncthreads();

    float c0[2][4], c1[2][4], cx[2][4];
#pragma unroll
    for (int nb = 0; nb < 2; nb++)
#pragma unroll
        for (int e = 0; e < 4; e++) { c0[nb][e] = 0.f; c1[nb][e] = 0.f; cx[nb][e] = 0.f; }

    for (int t = 0; t < NTILES; t++) {
        const float* buf = sm + (t & 1) * BUFF;
        const float* Ahi = buf;
        const float* Alo = buf + OFF_ALO;
        const float* Bhi = buf + OFF_BHI;
        const float* Blo = buf + OFF_BLO;

        if (t < NTILES - 1) {
            const int k0 = (t + 1) * TBK;
            xa = *(const float4*)&x[(mBase + rowA) * INPUT_DIM + k0 + kcA];
#pragma unroll
            for (int l = 0; l < 2; l++)
                wb[l] = *(const float4*)&W[(nBase + rowB[l]) * INPUT_DIM + k0 + kcB[l]];
        }

#pragma unroll
        for (int s = 0; s < 4; s++) {
            const int ka = s * 8 + q;
            const uint32_t a0h = __float_as_uint(Ahi[ar0 + ka]);
            const uint32_t a1h = __float_as_uint(Ahi[ar1 + ka]);
            const uint32_t a2h = __float_as_uint(Ahi[ar0 + ka + 4]);
            const uint32_t a3h = __float_as_uint(Ahi[ar1 + ka + 4]);
            const uint32_t a0l = __float_as_uint(Alo[ar0 + ka]);
            const uint32_t a1l = __float_as_uint(Alo[ar1 + ka]);
            const uint32_t a2l = __float_as_uint(Alo[ar0 + ka + 4]);
            const uint32_t a3l = __float_as_uint(Alo[ar1 + ka + 4]);

            float (*cm)[4] = (s & 1) ? c1 : c0;

#pragma unroll
            for (int nb = 0; nb < 2; nb++) {
                const int rb = (nh * 16 + nb * 8 + g) * ROWF + ka;
                const uint32_t b0h = __float_as_uint(Bhi[rb]);
                const uint32_t b1h = __float_as_uint(Bhi[rb + 4]);
                const uint32_t b0l = __float_as_uint(Blo[rb]);
                const uint32_t b1l = __float_as_uint(Blo[rb + 4]);

                mma_tf32(cm[nb], a0h, a1h, a2h, a3h, b0h, b1h);  // hi*hi
                mma_tf32(cx[nb], a0h, a1h, a2h, a3h, b0l, b1l);  // hi*lo
                mma_tf32(cx[nb], a0l, a1l, a2l, a3l, b0h, b1h);  // lo*hi
            }
        }

        if (t < NTILES - 1) {
            float* nbuf = sm + ((t + 1) & 1) * BUFF;
            cvt_store(nbuf, nbuf + OFF_ALO, rowA * ROWF + kcA, xa);
#pragma unroll
            for (int l = 0; l < 2; l++)
                cvt_store(nbuf + OFF_BHI, nbuf + OFF_BLO,
                          rowB[l] * ROWF + kcB[l], wb[l]);
            __syncthreads();
        }
    }

    // Epilogue: combine (RN), bias + sigmoid.
    const int m1 = mBase + mb * 16 + g;
    const int m2 = m1 + 8;
#pragma unroll
    for (int nb = 0; nb < 2; nb++) {
        const int col = nBase + nh * 16 + nb * 8 + 2 * q;
        const float2 bb = *(const float2*)&bias[col];

        const float z0 = (c0[nb][0] + c1[nb][0]) + cx[nb][0] + bb.x;
        const float z1 = (c0[nb][1] + c1[nb][1]) + cx[nb][1] + bb.y;
        const float z2 = (c0[nb][2] + c1[nb][2]) + cx[nb][2] + bb.x;
        const float z3 = (c0[nb][3] + c1[nb][3]) + cx[nb][3] + bb.y;

        float2 o1, o2;
        o1.x = 1.0f / (1.0f + __expf(-z0));
        o1.y = 1.0f / (1.0f + __expf(-z1));
        o2.x = 1.0f / (1.0f + __expf(-z2));
        o2.y = 1.0f / (1.0f + __expf(-z3));

        *(float2*)&rates[m1 * NUM_NEURONS + col] = o1;
        *(float2*)&rates[m2 * NUM_NEURONS + col] = o2;
    }
}

// ---------------------------------------------------------------------------
// Spike kernel: the proven 74%-of-DRAM streaming shape. grid (T, BATCH),
// 256 threads; one (b,t) neuron row per block. Plain stream ordering after
// the GEMM. u reads hit L2 for the prefetched region.
// ---------------------------------------------------------------------------
__global__ __launch_bounds__(256)
void spike_kernel(const float4* __restrict__ u,
                  const float4* __restrict__ rates,
                  float4* __restrict__ spikes) {
    const int b = blockIdx.y;
    const long long base = (long long)(b * TIME_STEPS + blockIdx.x) * (NUM_NEURONS / 4);
    const int j = threadIdx.x * 2;

    const float4 u0 = __ldcs(&u[base + j]);
    const float4 u1 = __ldcs(&u[base + j + 1]);

    const float4* rrow = rates + b * (NUM_NEURONS / 4);
    const float4 r0 = __ldg(&rrow[j]);
    const float4 r1 = __ldg(&rrow[j + 1]);

    float4 s0, s1;
    s0.x = (u0.x < r0.x) ? 1.0f : 0.0f;
    s0.y = (u0.y < r0.y) ? 1.0f : 0.0f;
    s0.z = (u0.z < r0.z) ? 1.0f : 0.0f;
    s0.w = (u0.w < r0.w) ? 1.0f : 0.0f;
    s1.x = (u1.x < r1.x) ? 1.0f : 0.0f;
    s1.y = (u1.y < r1.y) ? 1.0f : 0.0f;
    s1.z = (u1.z < r1.z) ? 1.0f : 0.0f;
    s1.w = (u1.w < r1.w) ? 1.0f : 0.0f;

    __stcs(&spikes[base + j], s0);
    __stcs(&spikes[base + j + 1], s1);
}

extern "C" void kernel_launch(void* const* d_in, const int* in_sizes, int n_in,
                              void* d_out, int out_size) {
    const float* x = (const float*)d_in[0];
    const float* W = (const float*)d_in[1];
    const float* b = (const float*)d_in[2];
    const float* u = (const float*)d_in[3];

    float* out    = (float*)d_out;
    float* spikes = out;                                               // 52,428,800
    float* rates  = out + (long long)BATCH * TIME_STEPS * NUM_NEURONS; // +524,288

    // Lazy one-time host objects (no device memory).
    static cudaStream_t sPf;
    static cudaEvent_t  eFork, eJoin;
    static bool inited = false;
    if (!inited) {
        cudaStreamCreateWithFlags(&sPf, cudaStreamNonBlocking);
        cudaEventCreateWithFlags(&eFork, cudaEventDisableTiming);
        cudaEventCreateWithFlags(&eJoin, cudaEventDisableTiming);
        cudaFuncSetAttribute(rates_kernel,
                             cudaFuncAttributeMaxDynamicSharedMemorySize, SMEM_BYTES);
        inited = true;
    }

    // Fork: prefetch branch runs concurrently with the GEMM.
    cudaEventRecord(eFork, 0);
    cudaStreamWaitEvent(sPf, eFork, 0);
    prefetch_kernel<<<PF_BLOCKS, 256, 0, sPf>>>((const char*)u);

    // Main stream: GEMM, then the spike stream (plain stream ordering).
    dim3 gGrid(NUM_NEURONS / TBN, BATCH / TBM);    // (32, 8) = 256 blocks
    rates_kernel<<<gGrid, 256, SMEM_BYTES, 0>>>(x, W, b, rates);

    spike_kernel<<<dim3(TIME_STEPS, BATCH, 1), 256>>>(
        (const float4*)u, (const float4*)rates, (float4*)spikes);

    // Join the prefetch branch.
    cudaEventRecord(eJoin, sPf);
    cudaStreamWaitEvent(0, eJoin, 0);
}

// round 17
// speedup vs baseline: 1.0917x; 1.0917x over previous
#include <cuda_runtime.h>
#include <cuda_bf16.h>
#include <cstdint>

// SpikeEncoder: rates = sigmoid(x @ W^T + b); spikes = (u < rates)
// x: [256,512] f32, W: [2048,512] f32, b: [2048] f32, u: [256,100,2048] f32
// out: spikes [256*100*2048] f32, then rates [256*2048] f32

#define BATCH 256
#define INPUT_DIM 512
#define NUM_NEURONS 2048
#define TIME_STEPS 100

#define MCHUNK 128                 // batch rows per pipeline stage (2 stages)

#define TBM 32                     // GEMM tile rows
#define TBN 64
#define TBK 32
#define NTILES (INPUT_DIM / TBK)   // 16
#define NSTAGE 3

#define ROWF 36                    // padded floats per smem row (bank-bijective)
#define TILEF_A (TBM * ROWF)       // 1152 floats
#define TILEF_B (TBN * ROWF)       // 2304 floats
#define STAGEF (TILEF_A + TILEF_B) // 3456 floats = 13824 B per stage
#define SMEM_BYTES (NSTAGE * STAGEF * 4)   // 41472 B

__device__ __forceinline__ void cp_async16(uint32_t smem_addr, const void* gmem) {
    asm volatile("cp.async.cg.shared.global [%0], [%1], 16;\n"
                 :: "r"(smem_addr), "l"(gmem));
}
__device__ __forceinline__ void cp_commit() {
    asm volatile("cp.async.commit_group;\n" ::: "memory");
}
__device__ __forceinline__ void cp_wait1() {
    asm volatile("cp.async.wait_group 1;\n" ::: "memory");
}
__device__ __forceinline__ void cp_wait0() {
    asm volatile("cp.async.wait_group 0;\n" ::: "memory");
}

// On-the-fly tf32 split (identical per-value math to the verified
// split-at-store kernel): hi = mantissa mask (one LOP3, exact);
// lo = cvt.rna.tf32(v - hi).
__device__ __forceinline__ void frag_split(float v, uint32_t& h, uint32_t& l) {
    h = __float_as_uint(v) & 0xFFFFE000u;
    asm("cvt.rna.tf32.f32 %0, %1;" : "=r"(l) : "f"(v - __uint_as_float(h)));
}

// D += A(tf32, m16k8 row) x B(tf32, k8n8 col)
__device__ __forceinline__ void mma_tf32(float c[4],
                                         uint32_t a0, uint32_t a1,
                                         uint32_t a2, uint32_t a3,
                                         uint32_t b0, uint32_t b1) {
    asm volatile(
        "mma.sync.aligned.m16n8k8.row.col.f32.tf32.tf32.f32 "
        "{%0,%1,%2,%3}, {%4,%5,%6,%7}, {%8,%9}, {%0,%1,%2,%3};"
        : "+f"(c[0]), "+f"(c[1]), "+f"(c[2]), "+f"(c[3])
        : "r"(a0), "r"(a1), "r"(a2), "r"(a3), "r"(b0), "r"(b1));
}

// ---------------------------------------------------------------------------
// GEMM chunk: rates[mBase0 .. mBase0+127] = sigmoid(x @ W^T + b).
// 32x64 tile, grid (32, 4) = 128 blocks (1 block/SM), 256 threads, 8 warps.
// cp.async 3-stage pipeline of RAW fp32 tiles; tf32 split at fragment-load
// time. Accumulation order identical to the thrice-verified kernel
// (hi*hi -> c0/c1 even/odd k8; both cross terms chained into cx).
// RACE FIX: the FINAL tile needs wait_group 0 (only 1 group remains in
// flight there, so wait_group 1 returned before the tile landed — the
// R14/R16 accuracy regressions were this race, not the math).
// ---------------------------------------------------------------------------
__global__ __launch_bounds__(256)
void rates_chunk_kernel(const float* __restrict__ x,
                        const float* __restrict__ W,
                        const float* __restrict__ bias,
                        float* __restrict__ rates,
                        int mBase0) {
    extern __shared__ float sm[];

    const int tid  = threadIdx.x;
    const int warp = tid >> 5;
    const int lane = tid & 31;
    const int g = lane >> 2;
    const int q = lane & 3;
    const int mb = warp & 1;       // m16 block (0..1)
    const int nh = warp >> 1;      // n16 group (0..3)

    const int nBase = blockIdx.x * TBN;
    const int mBase = mBase0 + blockIdx.y * TBM;

    // Cooperative cp.async coords. A: 256 16B-chunks (1/thread); B: 512 (2/thread)
    const int rowA = tid >> 3;             // 0..31
    const int kcA  = (tid & 7) * 4;
    int rowB[2], kcB[2];
#pragma unroll
    for (int l = 0; l < 2; l++) {
        const int f = tid + l * 256;
        rowB[l] = f >> 3;                  // 0..63
        kcB[l]  = (f & 7) * 4;
    }

    const uint32_t sBase = (uint32_t)__cvta_generic_to_shared(sm);
    const uint32_t dA  = sBase + (uint32_t)(rowA * ROWF + kcA) * 4u;
    uint32_t dB[2];
#pragma unroll
    for (int l = 0; l < 2; l++)
        dB[l] = sBase + (uint32_t)(TILEF_A + rowB[l] * ROWF + kcB[l]) * 4u;
    const uint32_t stageB = (uint32_t)STAGEF * 4u;

    // Prologue: issue stages 0 and 1
#pragma unroll
    for (int p = 0; p < 2; p++) {
        const int k0 = p * TBK;
        const uint32_t so = (uint32_t)p * stageB;
        cp_async16(dA + so, &x[(mBase + rowA) * INPUT_DIM + k0 + kcA]);
#pragma unroll
        for (int l = 0; l < 2; l++)
            cp_async16(dB[l] + so, &W[(nBase + rowB[l]) * INPUT_DIM + k0 + kcB[l]]);
        cp_commit();
    }

    // Accumulators: c0/c1 = hi*hi even/odd k8; cx = BOTH cross terms
    float c0[2][4], c1[2][4], cx[2][4];
#pragma unroll
    for (int nb = 0; nb < 2; nb++)
#pragma unroll
        for (int e = 0; e < 4; e++) { c0[nb][e] = 0.f; c1[nb][e] = 0.f; cx[nb][e] = 0.f; }

    const int ar0 = (mb * 16 + g) * ROWF;
    const int ar1 = ar0 + 8 * ROWF;

    for (int t = 0; t < NTILES; t++) {
        if (t == NTILES - 1) cp_wait0();   // last tile: drain ALL groups
        else                 cp_wait1();   // stage t landed (1 still in flight)
        __syncthreads();

        if (t + 2 < NTILES) {
            const int k0 = (t + 2) * TBK;
            const uint32_t so = (uint32_t)((t + 2) % NSTAGE) * stageB;
            cp_async16(dA + so, &x[(mBase + rowA) * INPUT_DIM + k0 + kcA]);
#pragma unroll
            for (int l = 0; l < 2; l++)
                cp_async16(dB[l] + so, &W[(nBase + rowB[l]) * INPUT_DIM + k0 + kcB[l]]);
            cp_commit();
        }

        const float* Ar = sm + (t % NSTAGE) * STAGEF;
        const float* Br = Ar + TILEF_A;

#pragma unroll
        for (int s = 0; s < 4; s++) {           // 4 k8 steps per tile
            const int ka = s * 8 + q;

            const float a0r = Ar[ar0 + ka];
            const float a1r = Ar[ar1 + ka];
            const float a2r = Ar[ar0 + ka + 4];
            const float a3r = Ar[ar1 + ka + 4];
            uint32_t a0h, a0l, a1h, a1l, a2h, a2l, a3h, a3l;
            frag_split(a0r, a0h, a0l);
            frag_split(a1r, a1h, a1l);
            frag_split(a2r, a2h, a2l);
            frag_split(a3r, a3h, a3l);

            float (*cm)[4] = (s & 1) ? c1 : c0;

#pragma unroll
            for (int nb = 0; nb < 2; nb++) {
                const int rb = (nh * 16 + nb * 8 + g) * ROWF + ka;
                const float b0r = Br[rb];
                const float b1r = Br[rb + 4];
                uint32_t b0h, b0l, b1h, b1l;
                frag_split(b0r, b0h, b0l);
                frag_split(b1r, b1h, b1l);

                mma_tf32(cm[nb], a0h, a1h, a2h, a3h, b0h, b1h);  // hi*hi
                mma_tf32(cx[nb], a0h, a1h, a2h, a3h, b0l, b1l);  // hi*lo
                mma_tf32(cx[nb], a0l, a1l, a2l, a3l, b0h, b1h);  // lo*hi
            }
        }
    }

    // Epilogue: combine (RN), bias + sigmoid.
    // c[nb]: {C[g][2q], C[g][2q+1], C[g+8][2q], C[g+8][2q+1]}
    const int m1 = mBase + mb * 16 + g;
    const int m2 = m1 + 8;
#pragma unroll
    for (int nb = 0; nb < 2; nb++) {
        const int col = nBase + nh * 16 + nb * 8 + 2 * q;
        const float2 bb = *(const float2*)&bias[col];

        const float z0 = (c0[nb][0] + c1[nb][0]) + cx[nb][0] + bb.x;
        const float z1 = (c0[nb][1] + c1[nb][1]) + cx[nb][1] + bb.y;
        const float z2 = (c0[nb][2] + c1[nb][2]) + cx[nb][2] + bb.x;
        const float z3 = (c0[nb][3] + c1[nb][3]) + cx[nb][3] + bb.y;

        float2 o1, o2;
        o1.x = 1.0f / (1.0f + __expf(-z0));
        o1.y = 1.0f / (1.0f + __expf(-z1));
        o2.x = 1.0f / (1.0f + __expf(-z2));
        o2.y = 1.0f / (1.0f + __expf(-z3));

        *(float2*)&rates[m1 * NUM_NEURONS + col] = o1;
        *(float2*)&rates[m2 * NUM_NEURONS + col] = o2;
    }
}

// ---------------------------------------------------------------------------
// Spike chunk: b in [b0, b0+127]. grid (T, 128), 256 threads; one (b,t)
// neuron row per block (the proven 74%-of-DRAM shape).
// ---------------------------------------------------------------------------
__global__ __launch_bounds__(256)
void spike_chunk_kernel(const float4* __restrict__ u,
                        const float4* __restrict__ rates,
                        float4* __restrict__ spikes,
                        int b0) {
    const int b = b0 + blockIdx.y;
    const long long base = (long long)(b * TIME_STEPS + blockIdx.x) * (NUM_NEURONS / 4);
    const int j = threadIdx.x * 2;

    const float4 u0 = __ldcs(&u[base + j]);
    const float4 u1 = __ldcs(&u[base + j + 1]);

    const float4* rrow = rates + b * (NUM_NEURONS / 4);
    const float4 r0 = __ldg(&rrow[j]);
    const float4 r1 = __ldg(&rrow[j + 1]);

    float4 s0, s1;
    s0.x = (u0.x < r0.x) ? 1.0f : 0.0f;
    s0.y = (u0.y < r0.y) ? 1.0f : 0.0f;
    s0.z = (u0.z < r0.z) ? 1.0f : 0.0f;
    s0.w = (u0.w < r0.w) ? 1.0f : 0.0f;
    s1.x = (u1.x < r1.x) ? 1.0f : 0.0f;
    s1.y = (u1.y < r1.y) ? 1.0f : 0.0f;
    s1.z = (u1.z < r1.z) ? 1.0f : 0.0f;
    s1.w = (u1.w < r1.w) ? 1.0f : 0.0f;

    __stcs(&spikes[base + j], s0);
    __stcs(&spikes[base + j + 1], s1);
}

extern "C" void kernel_launch(void* const* d_in, const int* in_sizes, int n_in,
                              void* d_out, int out_size) {
    const float* x = (const float*)d_in[0];
    const float* W = (const float*)d_in[1];
    const float* b = (const float*)d_in[2];
    const float* u = (const float*)d_in[3];

    float* out    = (float*)d_out;
    float* spikes = out;                                               // 52,428,800
    float* rates  = out + (long long)BATCH * TIME_STEPS * NUM_NEURONS; // +524,288

    // Lazy one-time host objects (no device memory).
    static cudaStream_t s1;
    static cudaEvent_t  eG0, eG1;
    static bool inited = false;
    if (!inited) {
        cudaStreamCreateWithFlags(&s1, cudaStreamNonBlocking);
        cudaEventCreateWithFlags(&eG0, cudaEventDisableTiming);
        cudaEventCreateWithFlags(&eG1, cudaEventDisableTiming);
        cudaFuncSetAttribute(rates_chunk_kernel,
                             cudaFuncAttributeMaxDynamicSharedMemorySize, SMEM_BYTES);
        inited = true;
    }

    const float4* u4 = (const float4*)u;
    const float4* r4 = (const float4*)rates;
    float4*       s4 = (float4*)spikes;

    dim3 gGrid(NUM_NEURONS / TBN, MCHUNK / TBM);   // (32, 4) = 128 blocks
    dim3 sGrid(TIME_STEPS, MCHUNK);                // (100, 128)

    // Stage 0 GEMM alone on the chip (1 block/SM, minimal latency).
    rates_chunk_kernel<<<gGrid, 256, SMEM_BYTES, 0>>>(x, W, b, rates, 0);
    cudaEventRecord(eG0, 0);

    // Stage 1 GEMM on the side stream, AFTER G0 (so G0 isn't contended);
    // it runs hidden under S0's memory-bound window.
    cudaStreamWaitEvent(s1, eG0, 0);
    rates_chunk_kernel<<<gGrid, 256, SMEM_BYTES, s1>>>(x, W, b, rates, MCHUNK);
    cudaEventRecord(eG1, s1);

    // S0 on the main stream (after G0 by stream order), then S1 after eG1.
    spike_chunk_kernel<<<sGrid, 256, 0, 0>>>(u4, r4, s4, 0);
    cudaStreamWaitEvent(0, eG1, 0);
    spike_chunk_kernel<<<sGrid, 256, 0, 0>>>(u4, r4, s4, MCHUNK);
}